// round 1
// baseline (speedup 1.0000x reference)
#include <cuda_runtime.h>
#include <math.h>

#define THREADS 128
#define BM 64
#define BN 64
#define DH 64
#define TM 8
#define TN 4

// XOR swizzle on float4 granularity: row r, float4-col c4 (0..15).
// Rows are accessed at stride 4 in the S-gemm (r = tx*4+j), so swizzle key is r>>2.
__device__ __forceinline__ int swz(int r, int c4) {
    return (r << 4) + (c4 ^ ((r >> 2) & 15));
}

__global__ __launch_bounds__(THREADS, 3)
void gat_fp32_kernel(const float* __restrict__ Q, const float* __restrict__ K,
                     const float* __restrict__ V, const int* __restrict__ adj,
                     float* __restrict__ out, int N)
{
    extern __shared__ float4 sm4[];
    float4* Qs = sm4;                 // BM x 16 float4
    float4* Ks = Qs + BM * (DH / 4);  // BN x 16
    float4* Vs = Ks + BN * (DH / 4);  // BN x 16
    float4* Ps = Vs + BN * (DH / 4);  // BM x 16

    const int bh   = blockIdx.y;
    const int row0 = blockIdx.x * BM;

    const float4* Qb = reinterpret_cast<const float4*>(Q) + (size_t)bh * N * (DH / 4);
    const float4* Kb = reinterpret_cast<const float4*>(K) + (size_t)bh * N * (DH / 4);
    const float4* Vb = reinterpret_cast<const float4*>(V) + (size_t)bh * N * (DH / 4);

    const int tid = threadIdx.x;
    const int ty  = tid >> 4;   // 0..7  -> rows ty*8 .. ty*8+7
    const int tx  = tid & 15;   // 0..15 -> key-cols / d-cols tx*4 .. tx*4+3

    // ---- load Q tile (coalesced, swizzled store) ----
    #pragma unroll
    for (int i = tid; i < BM * DH / 4; i += THREADS) {
        int r = i >> 4, c4 = i & 15;
        Qs[swz(r, c4)] = Qb[(size_t)(row0 + r) * (DH / 4) + c4];
    }

    float acc[TM][TN];
    float m_i[TM], l_i[TM];
    #pragma unroll
    for (int i = 0; i < TM; i++) {
        m_i[i] = -INFINITY;
        l_i[i] = 0.0f;
        #pragma unroll
        for (int j = 0; j < TN; j++) acc[i][j] = 0.0f;
    }

    const int nTiles = N / BN;
    for (int t = 0; t < nTiles; t++) {
        const int col0 = t * BN;

        __syncthreads();  // protect Ks/Vs/Ps from previous iteration's readers
        #pragma unroll
        for (int i = tid; i < BN * DH / 4; i += THREADS) {
            int r = i >> 4, c4 = i & 15;
            Ks[swz(r, c4)] = Kb[(size_t)(col0 + r) * (DH / 4) + c4];
            Vs[swz(r, c4)] = Vb[(size_t)(col0 + r) * (DH / 4) + c4];
        }
        __syncthreads();

        // ---- S = Q K^T (8x4 fragment per thread) ----
        float s[TM][TN];
        #pragma unroll
        for (int i = 0; i < TM; i++)
            #pragma unroll
            for (int j = 0; j < TN; j++) s[i][j] = 0.0f;

        #pragma unroll
        for (int k4 = 0; k4 < DH / 4; k4++) {
            float4 kv[TN];
            #pragma unroll
            for (int j = 0; j < TN; j++) kv[j] = Ks[swz(tx * TN + j, k4)];
            #pragma unroll
            for (int i = 0; i < TM; i++) {
                float4 qv = Qs[swz(ty * TM + i, k4)];
                #pragma unroll
                for (int j = 0; j < TN; j++) {
                    s[i][j] = fmaf(qv.x, kv[j].x, s[i][j]);
                    s[i][j] = fmaf(qv.y, kv[j].y, s[i][j]);
                    s[i][j] = fmaf(qv.z, kv[j].z, s[i][j]);
                    s[i][j] = fmaf(qv.w, kv[j].w, s[i][j]);
                }
            }
        }

        // ---- mask + scale + online softmax update ----
        #pragma unroll
        for (int i = 0; i < TM; i++) {
            const int row = row0 + ty * TM + i;
            const int4 a = *reinterpret_cast<const int4*>(
                adj + (size_t)row * N + col0 + tx * TN);
            s[i][0] = (a.x > 0) ? s[i][0] * 0.125f : -9e15f;
            s[i][1] = (a.y > 0) ? s[i][1] * 0.125f : -9e15f;
            s[i][2] = (a.z > 0) ? s[i][2] * 0.125f : -9e15f;
            s[i][3] = (a.w > 0) ? s[i][3] * 0.125f : -9e15f;

            float tmax = fmaxf(fmaxf(s[i][0], s[i][1]), fmaxf(s[i][2], s[i][3]));
            #pragma unroll
            for (int o = 8; o >= 1; o >>= 1)
                tmax = fmaxf(tmax, __shfl_xor_sync(0xffffffffu, tmax, o));

            const float nm = fmaxf(m_i[i], tmax);
            const float f  = __expf(m_i[i] - nm);
            m_i[i] = nm;

            float p0 = __expf(s[i][0] - nm);
            float p1 = __expf(s[i][1] - nm);
            float p2 = __expf(s[i][2] - nm);
            float p3 = __expf(s[i][3] - nm);
            float sum = (p0 + p1) + (p2 + p3);
            #pragma unroll
            for (int o = 8; o >= 1; o >>= 1)
                sum += __shfl_xor_sync(0xffffffffu, sum, o);

            l_i[i] = l_i[i] * f + sum;
            #pragma unroll
            for (int j = 0; j < TN; j++) acc[i][j] *= f;

            Ps[swz(ty * TM + i, tx)] = make_float4(p0, p1, p2, p3);
        }
        __syncthreads();

        // ---- acc += P @ V  (8 rows x 4 d-cols per thread) ----
        #pragma unroll
        for (int c4 = 0; c4 < BN / 4; c4++) {
            float4 vv[4];
            #pragma unroll
            for (int cc = 0; cc < 4; cc++) vv[cc] = Vs[swz(c4 * 4 + cc, tx)];
            #pragma unroll
            for (int i = 0; i < TM; i++) {
                float4 p4 = Ps[swz(ty * TM + i, c4)];
                acc[i][0] = fmaf(p4.x, vv[0].x, acc[i][0]);
                acc[i][0] = fmaf(p4.y, vv[1].x, acc[i][0]);
                acc[i][0] = fmaf(p4.z, vv[2].x, acc[i][0]);
                acc[i][0] = fmaf(p4.w, vv[3].x, acc[i][0]);
                acc[i][1] = fmaf(p4.x, vv[0].y, acc[i][1]);
                acc[i][1] = fmaf(p4.y, vv[1].y, acc[i][1]);
                acc[i][1] = fmaf(p4.z, vv[2].y, acc[i][1]);
                acc[i][1] = fmaf(p4.w, vv[3].y, acc[i][1]);
                acc[i][2] = fmaf(p4.x, vv[0].z, acc[i][2]);
                acc[i][2] = fmaf(p4.y, vv[1].z, acc[i][2]);
                acc[i][2] = fmaf(p4.z, vv[2].z, acc[i][2]);
                acc[i][2] = fmaf(p4.w, vv[3].z, acc[i][2]);
                acc[i][3] = fmaf(p4.x, vv[0].w, acc[i][3]);
                acc[i][3] = fmaf(p4.y, vv[1].w, acc[i][3]);
                acc[i][3] = fmaf(p4.z, vv[2].w, acc[i][3]);
                acc[i][3] = fmaf(p4.w, vv[3].w, acc[i][3]);
            }
        }
    }

    // ---- epilogue: normalize and store [B,H,N,D] contiguous (== reshape(N,B,H,D)) ----
    #pragma unroll
    for (int i = 0; i < TM; i++) {
        const float inv = 1.0f / l_i[i];
        const int row = row0 + ty * TM + i;
        float4 o = make_float4(acc[i][0] * inv, acc[i][1] * inv,
                               acc[i][2] * inv, acc[i][3] * inv);
        reinterpret_cast<float4*>(out)[((size_t)bh * N + row) * (DH / 4) + tx] = o;
    }
}

extern "C" void kernel_launch(void* const* d_in, const int* in_sizes, int n_in,
                              void* d_out, int out_size)
{
    const float* Q   = (const float*)d_in[0];
    const float* K   = (const float*)d_in[1];
    const float* V   = (const float*)d_in[2];
    const int*   adj = (const int*)d_in[3];
    float*       out = (float*)d_out;

    // N from adj element count (N*N); BH from Q element count (BH*N*D)
    const int N  = (int)(sqrt((double)in_sizes[3]) + 0.5);
    const int BH = in_sizes[0] / (N * DH);

    const size_t smem_bytes = 4u * 64u * 16u * sizeof(float4);  // 64 KB
    cudaFuncSetAttribute(gat_fp32_kernel,
                         cudaFuncAttributeMaxDynamicSharedMemorySize,
                         (int)smem_bytes);

    dim3 grid(N / BM, BH);
    gat_fp32_kernel<<<grid, THREADS, smem_bytes>>>(Q, K, V, adj, out, N);
}